// round 2
// baseline (speedup 1.0000x reference)
#include <cuda_runtime.h>
#include <cuda_bf16.h>
#include <math.h>

#define B_    2048
#define N_    4096
#define E_    256
#define H_    4
#define FS_   64
#define TILE  64
#define PADF  260          // 256 + 4 floats pad (row stride, 16B aligned)
#define JS    2
#define NJT   (N_ / (JS * TILE))   // 32 j-tiles per block
#define SMEM_BYTES (3 * TILE * PADF * 4)

static __device__ float    g_F[N_ * E_];      // normalized features, row-major [i][e]
static __device__ unsigned g_bits[B_];        // 10-bit label masks
static __device__ float    g_R[N_ * H_];      // sum_{j!=i} exp(dot/T)
static __device__ float    g_cnt[N_ * H_];    // positives count per (i, argmax head)
static __device__ float    g_dot[N_];         // sum mask * bestdot

// ---------------- helpers ----------------
__device__ __forceinline__ unsigned long long ffma2(unsigned long long a,
                                                    unsigned long long b,
                                                    unsigned long long c) {
    asm("fma.rn.f32x2 %0, %1, %2, %0;" : "+l"(c) : "l"(a), "l"(b));
    return c;
}
__device__ __forceinline__ float ex2f(float x) {
    float r; asm("ex2.approx.ftz.f32 %0, %1;" : "=f"(r) : "f"(x)); return r;
}
__device__ __forceinline__ void cpasync16(float* dst, const float4* src) {
    unsigned d = (unsigned)__cvta_generic_to_shared(dst);
    asm volatile("cp.async.cg.shared.global [%0], [%1], 16;" :: "r"(d), "l"(src));
}
__device__ __forceinline__ void loadTile(float* dst, int row0, int tid) {
#pragma unroll
    for (int t = 0; t < 16; ++t) {
        int idx = t * 256 + tid;
        int r   = idx >> 6;        // 64 float4 per row
        int c4  = idx & 63;
        const float4* src = (const float4*)(g_F + (row0 + r) * E_) + c4;
        cpasync16(dst + r * PADF + c4 * 4, src);
    }
}

// ---------------- preprocessing ----------------
__global__ void zeroK() {
    int t = blockIdx.x * blockDim.x + threadIdx.x;
    if (t < N_ * H_) { g_R[t] = 0.f; g_cnt[t] = 0.f; }
    if (t < N_) g_dot[t] = 0.f;
}

__global__ void bitsK(const float* __restrict__ labels) {
    int b = blockIdx.x * blockDim.x + threadIdx.x;
    if (b < B_) {
        unsigned m = 0;
#pragma unroll
        for (int k = 0; k < 10; ++k)
            if (labels[b * 10 + k] > 0.5f) m |= (1u << k);
        g_bits[b] = m;
    }
}

__global__ void normK(const float* __restrict__ feat) {
    int i = blockIdx.x;           // 0..4095   (i = v*B + b, view-major stacking)
    int e = threadIdx.x;          // 0..255
    int v = i >> 11, b = i & (B_ - 1);
    float val = feat[(b * 2 + v) * E_ + e];
    float sq = val * val;
#pragma unroll
    for (int o = 16; o; o >>= 1) sq += __shfl_xor_sync(0xffffffffu, sq, o);
    __shared__ float ws[8];
    if ((e & 31) == 0) ws[e >> 5] = sq;
    __syncthreads();
    int h = e >> 6;                          // per-head (64-dim) normalization
    float s  = ws[2 * h] + ws[2 * h + 1];
    float nm = sqrtf(s);
    float inv = 1.0f / fmaxf(nm, 1e-12f);
    g_F[i * E_ + e] = val * inv;
}

// ---------------- main tile compute ----------------
template <bool DIAG>
__device__ __forceinline__ void tileCompute(
    const float* __restrict__ As, const float* __restrict__ Bc,
    int j0, int ti, int tj,
    float (&R)[4][4], float (&cdot)[4], unsigned (&cp_)[4],
    const unsigned (&bI)[4])
{
    const float C2 = 20.60992915555662f;   // log2(e)/0.07
    unsigned bJ[4];
#pragma unroll
    for (int u = 0; u < 4; ++u)
        bJ[u] = g_bits[(j0 + tj + 16 * u) & (B_ - 1)];

    float best[4][4]; int bh[4][4];
#pragma unroll
    for (int a = 0; a < 4; ++a)
#pragma unroll
        for (int b = 0; b < 4; ++b) { best[a][b] = -3.0e38f; bh[a][b] = 0; }

#pragma unroll
    for (int h = 0; h < 4; ++h) {
        const float* ar[4]; const float* br[4];
#pragma unroll
        for (int u = 0; u < 4; ++u) {
            ar[u] = As + (ti + 16 * u) * PADF + h * FS_;
            br[u] = Bc + (tj + 16 * u) * PADF + h * FS_;
        }
        unsigned long long acc[4][4];
#pragma unroll
        for (int a = 0; a < 4; ++a)
#pragma unroll
            for (int b = 0; b < 4; ++b) acc[a][b] = 0ull;

#pragma unroll 4
        for (int kk = 0; kk < FS_; kk += 4) {
            ulonglong2 av[4], bv[4];
#pragma unroll
            for (int u = 0; u < 4; ++u) {
                av[u] = *(const ulonglong2*)(ar[u] + kk);
                bv[u] = *(const ulonglong2*)(br[u] + kk);
            }
#pragma unroll
            for (int a = 0; a < 4; ++a)
#pragma unroll
                for (int b = 0; b < 4; ++b) {
                    acc[a][b] = ffma2(av[a].x, bv[b].x, acc[a][b]);
                    acc[a][b] = ffma2(av[a].y, bv[b].y, acc[a][b]);
                }
        }
        // per-pair epilogue for this head
#pragma unroll
        for (int a = 0; a < 4; ++a)
#pragma unroll
            for (int b = 0; b < 4; ++b) {
                unsigned long long ac = acc[a][b];
                float lo = __uint_as_float((unsigned)ac);
                float hi = __uint_as_float((unsigned)(ac >> 32));
                float dt = lo + hi;                     // dot(i,j) for head h
                float e  = ex2f(dt * C2);               // exp(dot/T)
                if (DIAG && (ti + 16 * a) == (tj + 16 * b)) e = 0.f;
                R[a][h] += e;
                if (dt > best[a][b]) { best[a][b] = dt; bh[a][b] = h; }
            }
    }
    // masked accumulation (after all heads known)
#pragma unroll
    for (int a = 0; a < 4; ++a) {
        unsigned bi = bI[a];
#pragma unroll
        for (int b = 0; b < 4; ++b) {
            bool m = ((bi & bJ[b]) != 0u) &&
                     (!DIAG || ((ti + 16 * a) != (tj + 16 * b)));
            if (m) {
                cdot[a] += best[a][b];
                cp_[a]  += 1u << (bh[a][b] * 8);   // <=128 per 8-bit field
            }
        }
    }
}

__global__ void __launch_bounds__(256, 1) mainK() {
    extern __shared__ float sm[];
    float* As  = sm;
    float* Bs0 = sm + TILE * PADF;
    float* Bs1 = sm + 2 * TILE * PADF;

    const int tid    = threadIdx.x;
    const int ti     = tid >> 4;               // 0..15
    const int tj     = tid & 15;               // 0..15
    const int i_base = blockIdx.x * TILE;
    const int j_base = blockIdx.y * (NJT * TILE);

    loadTile(As,  i_base, tid);
    loadTile(Bs0, j_base, tid);
    asm volatile("cp.async.commit_group;" ::: "memory");

    unsigned bI[4];
    float R[4][4], cdot[4];
    unsigned cp_[4];
#pragma unroll
    for (int u = 0; u < 4; ++u) {
        bI[u] = g_bits[(i_base + ti + 16 * u) & (B_ - 1)];
        cdot[u] = 0.f; cp_[u] = 0u;
#pragma unroll
        for (int h = 0; h < 4; ++h) R[u][h] = 0.f;
    }

    for (int jt = 0; jt < NJT; ++jt) {
        float* Bc = (jt & 1) ? Bs1 : Bs0;
        if (jt + 1 < NJT) {
            loadTile((jt & 1) ? Bs0 : Bs1, j_base + (jt + 1) * TILE, tid);
            asm volatile("cp.async.commit_group;" ::: "memory");
            asm volatile("cp.async.wait_group 1;" ::: "memory");
        } else {
            asm volatile("cp.async.wait_group 0;" ::: "memory");
        }
        __syncthreads();
        const int j0 = j_base + jt * TILE;
        if (j0 == i_base)
            tileCompute<true >(As, Bc, j0, ti, tj, R, cdot, cp_, bI);
        else
            tileCompute<false>(As, Bc, j0, ti, tj, R, cdot, cp_, bI);
        __syncthreads();
    }

    // unpack counts, reduce across tj (xor 8,4,2,1 stays within half-warp), atomics
    float cntf[4][4];
#pragma unroll
    for (int u = 0; u < 4; ++u)
#pragma unroll
        for (int h = 0; h < 4; ++h)
            cntf[u][h] = (float)((cp_[u] >> (8 * h)) & 255u);

#pragma unroll
    for (int o = 8; o; o >>= 1) {
#pragma unroll
        for (int u = 0; u < 4; ++u) {
            cdot[u] += __shfl_xor_sync(0xffffffffu, cdot[u], o);
#pragma unroll
            for (int h = 0; h < 4; ++h) {
                R[u][h]    += __shfl_xor_sync(0xffffffffu, R[u][h], o);
                cntf[u][h] += __shfl_xor_sync(0xffffffffu, cntf[u][h], o);
            }
        }
    }
    if (tj == 0) {
#pragma unroll
        for (int u = 0; u < 4; ++u) {
            int gi = i_base + ti + 16 * u;
            atomicAdd(&g_dot[gi], cdot[u]);
#pragma unroll
            for (int h = 0; h < 4; ++h) {
                atomicAdd(&g_R[gi * 4 + h],   R[u][h]);
                atomicAdd(&g_cnt[gi * 4 + h], cntf[u][h]);
            }
        }
    }
}

// ---------------- finalize ----------------
__global__ void finalK(float* __restrict__ out) {
    __shared__ float ss[512], sc[512];
    int tid = threadIdx.x;
    float s = 0.f, c = 0.f;
    for (int i = tid; i < N_; i += 512) {
        float ct = 0.f;
        float acc = g_dot[i] * 14.285714285714286f;   // /T
#pragma unroll
        for (int h = 0; h < 4; ++h) {
            float cn = g_cnt[i * 4 + h];
            ct  += cn;
            acc -= cn * logf(g_R[i * 4 + h]);  // ln R = maxh + logS (exact cancellation)
        }
        float loss = -acc / ct;                 // NaN when ct==0, as in reference
        if (isfinite(loss)) { s += loss; c += 1.f; }
    }
    ss[tid] = s; sc[tid] = c;
    __syncthreads();
    for (int o = 256; o; o >>= 1) {
        if (tid < o) { ss[tid] += ss[tid + o]; sc[tid] += sc[tid + o]; }
        __syncthreads();
    }
    if (tid == 0) out[0] = ss[0] / sc[0];
}

// ---------------- launch ----------------
extern "C" void kernel_launch(void* const* d_in, const int* in_sizes, int n_in,
                              void* d_out, int out_size) {
    const float* features = (const float*)d_in[0];
    const float* labels   = (const float*)d_in[1];
    float* out = (float*)d_out;

    cudaFuncSetAttribute(mainK, cudaFuncAttributeMaxDynamicSharedMemorySize, SMEM_BYTES);

    zeroK<<<(N_ * H_ + 255) / 256, 256>>>();
    bitsK<<<(B_ + 255) / 256, 256>>>(labels);
    normK<<<N_, 256>>>(features);
    mainK<<<dim3(N_ / TILE, JS), 256, SMEM_BYTES>>>();
    finalK<<<1, 512>>>(out);
}

// round 3
// speedup vs baseline: 1.7996x; 1.7996x over previous
#include <cuda_runtime.h>
#include <cuda_bf16.h>
#include <math.h>

#define B_    2048
#define N_    4096
#define E_    256
#define H_    4
#define TI_   128
#define TJ_   64
#define JSPLIT 4
#define NTILE (N_/(JSPLIT*TJ_))    // 16 j-tiles per block
#define NCH   (NTILE*2)            // 32 half-chunks (2 heads each)
#define AFLOATS (TI_*E_)           // 32768
#define BFLOATS (TJ_*128)          // 8192
#define SMEM_BYTES ((AFLOATS + 2*BFLOATS)*4)   // 196608

static __device__ float    g_F[N_ * E_];      // normalized*sqrt(C2) features [i][e]
static __device__ unsigned g_bits[B_];        // 10-bit label masks
static __device__ float    g_R[N_ * H_];      // sum_{j!=i} exp(dot/T)
static __device__ float    g_cnt[N_ * H_];    // positives count per (i, argmax head)
static __device__ float    g_dot[N_];         // sum mask * bestdot_scaled

// ---------------- helpers ----------------
__device__ __forceinline__ unsigned long long ffma2(unsigned long long a,
                                                    unsigned long long b,
                                                    unsigned long long c) {
    asm("fma.rn.f32x2 %0, %1, %2, %0;" : "+l"(c) : "l"(a), "l"(b));
    return c;
}
__device__ __forceinline__ float ex2f(float x) {
    float r; asm("ex2.approx.ftz.f32 %0, %1;" : "=f"(r) : "f"(x)); return r;
}
__device__ __forceinline__ void cpasync16(float* dst, const float* src) {
    unsigned d = (unsigned)__cvta_generic_to_shared(dst);
    asm volatile("cp.async.cg.shared.global [%0], [%1], 16;" :: "r"(d), "l"(src));
}
// monotonic (bestdot, head) packing: order-preserving uint encoding, head in low 2 bits
__device__ __forceinline__ unsigned encMax(unsigned best, float dt, unsigned h) {
    unsigned u = __float_as_uint(dt);
    unsigned m = (unsigned)(((int)u) >> 31) | 0x80000000u;
    unsigned e = ((u ^ m) & 0xFFFFFFFCu) | h;
    return best > e ? best : e;
}
__device__ __forceinline__ float decDt(unsigned enc) {
    unsigned ue = enc & 0xFFFFFFFCu;
    unsigned m = (~(unsigned)(((int)enc) >> 31)) | 0x80000000u;
    return __uint_as_float(ue ^ m);
}

// A tile: [128][256] floats, float4-slot swizzle: slot = r*64 + (c4 ^ (r&7))
__device__ __forceinline__ void loadA(float* dst, int i0, int tid) {
#pragma unroll
    for (int t = 0; t < 32; ++t) {
        int idx = t * 256 + tid;
        int r = idx >> 6, c4 = idx & 63;
        int slot = r * 64 + (c4 ^ (r & 7));
        cpasync16(dst + slot * 4, g_F + (i0 + r) * E_ + c4 * 4);
    }
}
// B half tile: [64][128] floats, slot = r*32 + (c4 ^ (r&7))
__device__ __forceinline__ void loadB(float* dst, int j0, int half, int tid) {
#pragma unroll
    for (int t = 0; t < 8; ++t) {
        int idx = t * 256 + tid;
        int r = idx >> 5, c4 = idx & 31;
        int slot = r * 32 + (c4 ^ (r & 7));
        cpasync16(dst + slot * 4, g_F + (j0 + r) * E_ + half * 128 + c4 * 4);
    }
}

// ---------------- preprocessing ----------------
__global__ void zeroK() {
    int t = blockIdx.x * blockDim.x + threadIdx.x;
    if (t < N_ * H_) { g_R[t] = 0.f; g_cnt[t] = 0.f; }
    if (t < N_) g_dot[t] = 0.f;
}

__global__ void bitsK(const float* __restrict__ labels) {
    int b = blockIdx.x * blockDim.x + threadIdx.x;
    if (b < B_) {
        unsigned m = 0;
#pragma unroll
        for (int k = 0; k < 10; ++k)
            if (labels[b * 10 + k] > 0.5f) m |= (1u << k);
        g_bits[b] = m;
    }
}

__global__ void normK(const float* __restrict__ feat) {
    int i = blockIdx.x;           // 0..4095   (i = v*B + b, view-major stacking)
    int e = threadIdx.x;          // 0..255
    int v = i >> 11, b = i & (B_ - 1);
    float val = feat[(b * 2 + v) * E_ + e];
    float sq = val * val;
#pragma unroll
    for (int o = 16; o; o >>= 1) sq += __shfl_xor_sync(0xffffffffu, sq, o);
    __shared__ float ws[8];
    if ((e & 31) == 0) ws[e >> 5] = sq;
    __syncthreads();
    int h = e >> 6;                          // per-head (64-dim) normalization
    float s  = ws[2 * h] + ws[2 * h + 1];
    float inv = 1.0f / fmaxf(sqrtf(s), 1e-12f);
    // fold sqrt(log2(e)/T) into the features: dots come out pre-scaled by C2
    g_F[i * E_ + e] = val * inv * 4.53981654f;   // sqrt(20.60992915555662)
}

// ---------------- main compute: one half-chunk (2 heads) ----------------
template <int HALF>
__device__ __forceinline__ void computeChunk(
    const float* __restrict__ As, const float* __restrict__ Bc,
    int i_base, int j0, int ti, int tj,
    float (&R)[8][4], unsigned (&bp)[8][4],
    float (&cdot)[8], unsigned (&cp_)[8], const unsigned (&bI)[8])
{
    const int sB = tj & 7;
    const int sA = ti & 7;
    const bool diagP = ((unsigned)(j0 - i_base)) < (unsigned)TI_;
    const float* aB = As + ti * E_;
    const float* bB = Bc + tj * 128;

#pragma unroll
    for (int h2 = 0; h2 < 2; ++h2) {
        const int hh = HALF * 2 + h2;
        unsigned long long acc[8][4];
#pragma unroll
        for (int u = 0; u < 8; ++u)
#pragma unroll
            for (int v = 0; v < 4; ++v) acc[u][v] = 0ull;
        const float* aP = aB + hh * 64;
        const float* bP = bB + h2 * 64;
#pragma unroll
        for (int k4 = 0; k4 < 16; ++k4) {
            const int xb = (k4 ^ sB) * 4;
            const int xa = (k4 ^ sA) * 4;
            ulonglong2 bv[4];
#pragma unroll
            for (int v = 0; v < 4; ++v)
                bv[v] = *(const ulonglong2*)(bP + v * 2048 + xb);
            ulonglong2 av[8];
#pragma unroll
            for (int u = 0; u < 8; ++u)
                av[u] = *(const ulonglong2*)(aP + u * 4096 + xa);
#pragma unroll
            for (int u = 0; u < 8; ++u)
#pragma unroll
                for (int v = 0; v < 4; ++v) {
                    acc[u][v] = ffma2(av[u].x, bv[v].x, acc[u][v]);
                    acc[u][v] = ffma2(av[u].y, bv[v].y, acc[u][v]);
                }
        }
#pragma unroll
        for (int u = 0; u < 8; ++u)
#pragma unroll
            for (int v = 0; v < 4; ++v) {
                float lo = __uint_as_float((unsigned)(acc[u][v] & 0xFFFFFFFFull));
                float hi = __uint_as_float((unsigned)(acc[u][v] >> 32));
                float dt = lo + hi;              // = dot(i,j,hh) * log2(e)/T
                float e  = ex2f(dt);             // = exp(dot/T)
                if (diagP && (i_base + ti + 16 * u) == (j0 + tj + 16 * v)) e = 0.f;
                R[u][hh] += e;
                bp[u][v] = encMax(bp[u][v], dt, (unsigned)hh);
            }
    }

    if (HALF == 1) {   // all 4 heads seen for this tile: masked accumulation
        unsigned bJ[4];
#pragma unroll
        for (int v = 0; v < 4; ++v)
            bJ[v] = g_bits[(j0 + tj + 16 * v) & (B_ - 1)];
#pragma unroll
        for (int u = 0; u < 8; ++u) {
#pragma unroll
            for (int v = 0; v < 4; ++v) {
                bool m = ((bI[u] & bJ[v]) != 0u);
                if (diagP && (i_base + ti + 16 * u) == (j0 + tj + 16 * v)) m = false;
                if (m) {
                    unsigned e = bp[u][v];
                    cdot[u] += decDt(e);
                    cp_[u]  += 1u << ((e & 3u) * 8);
                }
                bp[u][v] = 0u;   // 0 < any real encoding
            }
        }
    }
}

__global__ void __launch_bounds__(256, 1) mainK() {
    extern __shared__ float sm[];
    float* As = sm;
    float* Bb0 = sm + AFLOATS;
    float* Bb1 = sm + AFLOATS + BFLOATS;

    const int tid = threadIdx.x;
    const int ti = tid >> 4;       // 0..15 -> i rows ti+16u, u<8
    const int tj = tid & 15;       // 0..15 -> j rows tj+16v, v<4
    const int i_base = blockIdx.x * TI_;
    const int j_base = blockIdx.y * (NTILE * TJ_);

    loadA(As, i_base, tid);
    loadB(Bb0, j_base, 0, tid);
    asm volatile("cp.async.commit_group;" ::: "memory");
    loadB(Bb1, j_base, 1, tid);
    asm volatile("cp.async.commit_group;" ::: "memory");

    float R[8][4]; unsigned bp[8][4]; float cdot[8]; unsigned cp_[8]; unsigned bI[8];
#pragma unroll
    for (int u = 0; u < 8; ++u) {
        bI[u] = g_bits[(i_base + ti + 16 * u) & (B_ - 1)];
        cdot[u] = 0.f; cp_[u] = 0u;
#pragma unroll
        for (int h = 0; h < 4; ++h) { R[u][h] = 0.f; bp[u][h] = 0u; }
    }

    for (int c = 0; c < NCH; ++c) {
        if (c == NCH - 1) asm volatile("cp.async.wait_group 0;" ::: "memory");
        else              asm volatile("cp.async.wait_group 1;" ::: "memory");
        __syncthreads();
        const int j0 = j_base + (c >> 1) * TJ_;
        const float* Bc = (c & 1) ? Bb1 : Bb0;
        if (c & 1) computeChunk<1>(As, Bc, i_base, j0, ti, tj, R, bp, cdot, cp_, bI);
        else       computeChunk<0>(As, Bc, i_base, j0, ti, tj, R, bp, cdot, cp_, bI);
        __syncthreads();
        if (c + 2 < NCH) {
            int cn = c + 2;
            loadB((c & 1) ? Bb1 : Bb0, j_base + (cn >> 1) * TJ_, cn & 1, tid);
            asm volatile("cp.async.commit_group;" ::: "memory");
        }
    }

    // reduce across the 16 tj-lanes (offsets 8..1 stay within the half-warp group)
    float cntf[8][4];
#pragma unroll
    for (int u = 0; u < 8; ++u)
#pragma unroll
        for (int h = 0; h < 4; ++h)
            cntf[u][h] = (float)((cp_[u] >> (8 * h)) & 255u);

#pragma unroll
    for (int o = 8; o; o >>= 1) {
#pragma unroll
        for (int u = 0; u < 8; ++u) {
            cdot[u] += __shfl_xor_sync(0xffffffffu, cdot[u], o);
#pragma unroll
            for (int h = 0; h < 4; ++h) {
                R[u][h]    += __shfl_xor_sync(0xffffffffu, R[u][h], o);
                cntf[u][h] += __shfl_xor_sync(0xffffffffu, cntf[u][h], o);
            }
        }
    }
    if (tj == 0) {
#pragma unroll
        for (int u = 0; u < 8; ++u) {
            int gi = i_base + ti + 16 * u;
            atomicAdd(&g_dot[gi], cdot[u]);
#pragma unroll
            for (int h = 0; h < 4; ++h) {
                atomicAdd(&g_R[gi * 4 + h],   R[u][h]);
                atomicAdd(&g_cnt[gi * 4 + h], cntf[u][h]);
            }
        }
    }
}

// ---------------- finalize ----------------
__global__ void finalK(float* __restrict__ out) {
    __shared__ float ss[512], sc[512];
    int tid = threadIdx.x;
    float s = 0.f, c = 0.f;
    for (int i = tid; i < N_; i += 512) {
        float ct = 0.f;
        // g_dot holds sum of scaled best dots (dot*log2e/T); *ln2 -> dot/T
        float acc = g_dot[i] * 0.6931471805599453f;
#pragma unroll
        for (int h = 0; h < 4; ++h) {
            float cn = g_cnt[i * 4 + h];
            ct  += cn;
            acc -= cn * logf(g_R[i * 4 + h]);  // ln R = maxh + logS (exact cancel)
        }
        float loss = -acc / ct;                 // NaN when ct==0, as in reference
        if (isfinite(loss)) { s += loss; c += 1.f; }
    }
    ss[tid] = s; sc[tid] = c;
    __syncthreads();
    for (int o = 256; o; o >>= 1) {
        if (tid < o) { ss[tid] += ss[tid + o]; sc[tid] += sc[tid + o]; }
        __syncthreads();
    }
    if (tid == 0) out[0] = ss[0] / sc[0];
}

// ---------------- launch ----------------
extern "C" void kernel_launch(void* const* d_in, const int* in_sizes, int n_in,
                              void* d_out, int out_size) {
    const float* features = (const float*)d_in[0];
    const float* labels   = (const float*)d_in[1];
    float* out = (float*)d_out;

    cudaFuncSetAttribute(mainK, cudaFuncAttributeMaxDynamicSharedMemorySize, SMEM_BYTES);

    zeroK<<<(N_ * H_ + 255) / 256, 256>>>();
    bitsK<<<(B_ + 255) / 256, 256>>>(labels);
    normK<<<N_, 256>>>(features);
    mainK<<<dim3(N_ / TI_, JSPLIT), 256, SMEM_BYTES>>>();
    finalK<<<1, 512>>>(out);
}